// round 14
// baseline (speedup 1.0000x reference)
#include <cuda_runtime.h>
#include <cuda_bf16.h>

#define CC 256
#define PD 16

// Per-batch broadcast vector y[b,c] (B=8, C=256), produced by cluster rank-0
// blocks, consumed by all via L2 (__ldcg). Duplicate writers (2 clusters per
// batch) write identical deterministic values — benign.
__device__ float g_y[8 * 256];

// ONE kernel, 128 blocks x 1024 threads, clusters of 8 (16 clusters; 2 per
// batch). Rank-0 of each cluster computes y for its batch (16 blocks x 512KB
// weight reads = 8MB L2) while ALL blocks front-issue their img loads; the
// hardware cluster barrier replaces the R7 software spin; then every block
// streams its 64-row slice: out = img + y (4 float4/thread).
__global__ __launch_bounds__(1024, 1) __cluster_dims__(8, 1, 1)
void fused_kernel(
    const float* __restrict__ param_tokens,  // (8,16)
    const float* __restrict__ Wparam,        // (16,256)
    const float* __restrict__ bparam,        // (256)
    const float* __restrict__ ctx_g,         // (256)
    const float* __restrict__ ctx_b,         // (256)
    const float* __restrict__ Wkv,           // (256,512)
    const float* __restrict__ Wout,          // (256,256)
    const float* __restrict__ bout,          // (256)
    const float4* __restrict__ img,          // (8,1024,64) as float4
    float4* __restrict__ out)
{
    const int bid  = blockIdx.x;
    const int b    = bid >> 4;      // batch 0..7
    const int rg   = bid & 15;      // row-group of 64 rows
    const int t    = threadIdx.x;
    const int c4   = t & 63;        // float4 column 0..63
    const int rsub = t >> 6;        // 0..15
    const int rank = bid & 7;       // cluster rank

    // float4 index of (b,row,c4) = b*65536 + row*64 + c4;
    // this thread's rows: rg*64 + rsub + 16*i, i=0..3 -> idx = base + 1024*i
    const int base = b * 65536 + (rg * 64 + rsub) * 64 + c4;

    // ── 1. front-issue the 4 HBM reads (overlap y compute + barrier) ──
    float4 x0 = img[base];
    float4 x1 = img[base + 1024];
    float4 x2 = img[base + 2048];
    float4 x3 = img[base + 3072];

    // ── 2. cluster rank-0 computes y[b] (4-way split reductions) ─────
    if (rank == 0) {
        const int col  = t & 255;
        const int r    = t >> 8;    // 0..3 reduction slice
        const int wrp  = t >> 5;
        const int lane = t & 31;

        __shared__ float s_ln[CC];
        __shared__ float s_v[CC];
        __shared__ float s_part[1024];
        __shared__ float s_red[32];

        // ctx[col] = param_tokens[b] @ Wparam + bparam
        float ctx = bparam[col];
#pragma unroll
        for (int p = 0; p < PD; p++)
            ctx = fmaf(param_tokens[b * PD + p], Wparam[p * CC + col], ctx);

        // mean (warps 0..7 cover cols 0..255 exactly)
        float s = ctx;
#pragma unroll
        for (int o = 16; o > 0; o >>= 1) s += __shfl_xor_sync(0xffffffffu, s, o);
        if (lane == 0) s_red[wrp] = s;
        __syncthreads();
        float tot = 0.0f;
#pragma unroll
        for (int w = 0; w < 8; w++) tot += s_red[w];
        const float mean = tot * (1.0f / 256.0f);
        const float d = ctx - mean;
        __syncthreads();  // protect s_red reuse

        // variance
        float sq = d * d;
#pragma unroll
        for (int o = 16; o > 0; o >>= 1) sq += __shfl_xor_sync(0xffffffffu, sq, o);
        if (lane == 0) s_red[wrp] = sq;
        __syncthreads();
        float vtot = 0.0f;
#pragma unroll
        for (int w = 0; w < 8; w++) vtot += s_red[w];
        const float var = vtot * (1.0f / 256.0f);

        const float ln = d * rsqrtf(var + 1e-5f) * ctx_g[col] + ctx_b[col];
        if (r == 0) s_ln[col] = ln;
        __syncthreads();

        // GEMV1: v[col] = sum_c ln[c]*Wkv[c,256+col], slice c in [64r,64r+64)
        {
            const float* __restrict__ Wk = Wkv + 256 + col;
            float v = 0.0f;
            const int c0 = r * 64;
#pragma unroll 16
            for (int c = c0; c < c0 + 64; c++)
                v = fmaf(s_ln[c], Wk[c * 512], v);
            s_part[t] = v;
        }
        __syncthreads();
        if (r == 0)
            s_v[col] = s_part[col] + s_part[col + 256] + s_part[col + 512] + s_part[col + 768];
        __syncthreads();

        // GEMV2: y[col] = sum_d v[d] * Wout[d,col] + bout[col]
        {
            float y = 0.0f;
            const int d0 = r * 64;
#pragma unroll 16
            for (int dd = d0; dd < d0 + 64; dd++)
                y = fmaf(s_v[dd], Wout[dd * CC + col], y);
            s_part[t] = y;
        }
        __syncthreads();
        if (r == 0)
            g_y[b * CC + col] = s_part[col] + s_part[col + 256] + s_part[col + 512]
                              + s_part[col + 768] + bout[col];
        __threadfence();  // g_y visible at L2 before our barrier arrive
    }

    // ── 3. hardware cluster barrier (no polling) ─────────────────────
    asm volatile("barrier.cluster.arrive.aligned;" ::: "memory");
    asm volatile("barrier.cluster.wait.aligned;" ::: "memory");

    // ── 4. add + store (y via L2, broadcast-friendly) ────────────────
    const float4 yv = __ldcg(&reinterpret_cast<const float4*>(g_y)[b * 64 + c4]);

    x0.x += yv.x; x0.y += yv.y; x0.z += yv.z; x0.w += yv.w;
    x1.x += yv.x; x1.y += yv.y; x1.z += yv.z; x1.w += yv.w;
    x2.x += yv.x; x2.y += yv.y; x2.z += yv.z; x2.w += yv.w;
    x3.x += yv.x; x3.y += yv.y; x3.z += yv.z; x3.w += yv.w;

    out[base]        = x0;
    out[base + 1024] = x1;
    out[base + 2048] = x2;
    out[base + 3072] = x3;
}

extern "C" void kernel_launch(void* const* d_in, const int* in_sizes, int n_in,
                              void* d_out, int out_size) {
    // 0 img_tokens (8,1024,256)   1 param_tokens (8,16)
    // 2 img_norm_g  3 img_norm_b  4 Wq (unused — cancels algebraically)
    // 5 Wparam (16,256)  6 bparam (256)
    // 7 ctx_norm_g (256) 8 ctx_norm_b (256)
    // 9 Wkv (256,512)   10 Wout (256,256)  11 bout (256)
    const float* img          = (const float*)d_in[0];
    const float* param_tokens = (const float*)d_in[1];
    const float* Wparam       = (const float*)d_in[5];
    const float* bparam       = (const float*)d_in[6];
    const float* ctx_g        = (const float*)d_in[7];
    const float* ctx_b        = (const float*)d_in[8];
    const float* Wkv          = (const float*)d_in[9];
    const float* Wout         = (const float*)d_in[10];
    const float* bout         = (const float*)d_in[11];

    fused_kernel<<<128, 1024>>>(param_tokens, Wparam, bparam, ctx_g, ctx_b,
                                Wkv, Wout, bout,
                                (const float4*)img, (float4*)d_out);
}

// round 15
// speedup vs baseline: 2.2825x; 2.2825x over previous
#include <cuda_runtime.h>
#include <cuda_bf16.h>

// Per-batch broadcast vector y[b, c] (B=8, C=256).
__device__ float g_y[8 * 256];

#define CC 256
#define PD 16

// PRIMARY: one block per batch, 1024 threads. Triggers PDL completion at the
// START so the dependent add kernel launches (and streams img from HBM)
// concurrently; the add kernel's cudaGridDependencySynchronize() waits for
// this grid to fully complete before reading g_y.
__global__ __launch_bounds__(1024) void compute_y_kernel(
    const float* __restrict__ param_tokens,  // (8,16)
    const float* __restrict__ Wparam,        // (16,256)
    const float* __restrict__ bparam,        // (256)
    const float* __restrict__ ctx_g,         // (256)
    const float* __restrict__ ctx_b,         // (256)
    const float* __restrict__ Wkv,           // (256,512)
    const float* __restrict__ Wout,          // (256,256)
    const float* __restrict__ bout)          // (256)
{
    // Release the dependent launch immediately — overlap is the whole point.
    cudaTriggerProgrammaticLaunchCompletion();

    const int b   = blockIdx.x;
    const int t   = threadIdx.x;   // 0..1023
    const int col = t & 255;       // output column
    const int r   = t >> 8;        // 0..3 reduction slice
    const int wrp = t >> 5;        // 0..31
    const int lane = t & 31;

    __shared__ float s_ln[CC];
    __shared__ float s_v[CC];
    __shared__ float s_part[1024];
    __shared__ float s_red[32];

    // ctx[col] — redundant across the 4 r-groups (cheap)
    float ctx = bparam[col];
#pragma unroll
    for (int p = 0; p < PD; p++)
        ctx = fmaf(param_tokens[b * PD + p], Wparam[p * CC + col], ctx);

    // mean (warps 0..7 cover cols 0..255 exactly)
    float s = ctx;
#pragma unroll
    for (int o = 16; o > 0; o >>= 1) s += __shfl_xor_sync(0xffffffffu, s, o);
    if (lane == 0) s_red[wrp] = s;
    __syncthreads();
    float tot = 0.0f;
#pragma unroll
    for (int w = 0; w < 8; w++) tot += s_red[w];
    const float mean = tot * (1.0f / 256.0f);
    const float d = ctx - mean;
    __syncthreads();  // protect s_red reuse

    // variance
    float sq = d * d;
#pragma unroll
    for (int o = 16; o > 0; o >>= 1) sq += __shfl_xor_sync(0xffffffffu, sq, o);
    if (lane == 0) s_red[wrp] = sq;
    __syncthreads();
    float vtot = 0.0f;
#pragma unroll
    for (int w = 0; w < 8; w++) vtot += s_red[w];
    const float var = vtot * (1.0f / 256.0f);

    const float ln = d * rsqrtf(var + 1e-5f) * ctx_g[col] + ctx_b[col];
    if (r == 0) s_ln[col] = ln;
    __syncthreads();

    // GEMV1: v[col] = sum_c ln[c] * Wkv[c, 256+col], slice c in [64r, 64r+64)
    {
        const float* __restrict__ Wk = Wkv + 256 + col;
        float v = 0.0f;
        const int c0 = r * 64;
#pragma unroll 16
        for (int c = c0; c < c0 + 64; c++)
            v = fmaf(s_ln[c], Wk[c * 512], v);
        s_part[t] = v;
    }
    __syncthreads();
    if (r == 0)
        s_v[col] = s_part[col] + s_part[col + 256] + s_part[col + 512] + s_part[col + 768];
    __syncthreads();

    // GEMV2: y[col] = sum_d v[d] * Wout[d, col] + bout[col]
    {
        float y = 0.0f;
        const int d0 = r * 64;
#pragma unroll 16
        for (int dd = d0; dd < d0 + 64; dd++)
            y = fmaf(s_v[dd], Wout[dd * CC + col], y);
        s_part[t] = y;
    }
    __syncthreads();
    if (r == 0)
        g_y[b * CC + col] = s_part[col] + s_part[col + 256] + s_part[col + 512]
                          + s_part[col + 768] + bout[col];
    // Grid completion itself is the release for the dependent kernel.
}

// SECONDARY (PDL): 128 blocks x 1024 threads, 4 float4/thread — one
// co-resident wave. All img loads are issued BEFORE the grid dependency
// sync, so the 16MB HBM read overlaps compute_y; the sync then guarantees
// g_y is complete and visible.
__global__ __launch_bounds__(1024, 1) void add_broadcast_kernel(
    const float4* __restrict__ img, float4* __restrict__ out)
{
    const int bid  = blockIdx.x;
    const int b    = bid >> 4;      // batch 0..7
    const int rg   = bid & 15;      // row-group of 64 rows
    const int t    = threadIdx.x;
    const int c4   = t & 63;        // float4 column 0..63
    const int rsub = t >> 6;        // 0..15

    // float4 index of (b,row,c4) = b*65536 + row*64 + c4;
    // rows = rg*64 + rsub + 16*i, i = 0..3 -> idx = base + 1024*i
    const int base = b * 65536 + (rg * 64 + rsub) * 64 + c4;

    float4 x0 = img[base];
    float4 x1 = img[base + 1024];
    float4 x2 = img[base + 2048];
    float4 x3 = img[base + 3072];

    cudaGridDependencySynchronize();  // waits for compute_y grid completion

    const float4 yv = __ldcg(&reinterpret_cast<const float4*>(g_y)[b * 64 + c4]);

    x0.x += yv.x; x0.y += yv.y; x0.z += yv.z; x0.w += yv.w;
    x1.x += yv.x; x1.y += yv.y; x1.z += yv.z; x1.w += yv.w;
    x2.x += yv.x; x2.y += yv.y; x2.z += yv.z; x2.w += yv.w;
    x3.x += yv.x; x3.y += yv.y; x3.z += yv.z; x3.w += yv.w;

    out[base]        = x0;
    out[base + 1024] = x1;
    out[base + 2048] = x2;
    out[base + 3072] = x3;
}

extern "C" void kernel_launch(void* const* d_in, const int* in_sizes, int n_in,
                              void* d_out, int out_size) {
    // 0 img_tokens (8,1024,256)   1 param_tokens (8,16)
    // 2 img_norm_g  3 img_norm_b  4 Wq (unused — cancels algebraically)
    // 5 Wparam (16,256)  6 bparam (256)
    // 7 ctx_norm_g (256) 8 ctx_norm_b (256)
    // 9 Wkv (256,512)   10 Wout (256,256)  11 bout (256)
    const float* img          = (const float*)d_in[0];
    const float* param_tokens = (const float*)d_in[1];
    const float* Wparam       = (const float*)d_in[5];
    const float* bparam       = (const float*)d_in[6];
    const float* ctx_g        = (const float*)d_in[7];
    const float* ctx_b        = (const float*)d_in[8];
    const float* Wkv          = (const float*)d_in[9];
    const float* Wout         = (const float*)d_in[10];
    const float* bout         = (const float*)d_in[11];

    compute_y_kernel<<<8, 1024>>>(param_tokens, Wparam, bparam, ctx_g, ctx_b,
                                  Wkv, Wout, bout);

    cudaLaunchConfig_t cfg = {};
    cfg.gridDim  = dim3(128, 1, 1);
    cfg.blockDim = dim3(1024, 1, 1);
    cfg.dynamicSmemBytes = 0;
    cfg.stream = 0;  // legacy default stream (same stream as primary)
    cudaLaunchAttribute attrs[1];
    attrs[0].id = cudaLaunchAttributeProgrammaticStreamSerialization;
    attrs[0].val.programmaticStreamSerializationAllowed = 1;
    cfg.attrs = attrs;
    cfg.numAttrs = 1;
    cudaLaunchKernelEx(&cfg, add_broadcast_kernel,
                       (const float4*)img, (float4*)d_out);
}